// round 12
// baseline (speedup 1.0000x reference)
#include <cuda_runtime.h>
#include <cuda_bf16.h>

#define G_MAX 128
#define BLOCK 256
#define SPLIT 4   // lanes per proposal; each scans G/SPLIT gt boxes

__global__ __launch_bounds__(BLOCK)
void roi_match_kernel(const float4* __restrict__ props,
                      const float4* __restrict__ gt,
                      const int*    __restrict__ gtl32,   // gt labels, i32 or i64 (auto-detect)
                      float*        __restrict__ out_labels,
                      float4*       __restrict__ out_boxes,
                      int N, int G)
{
    // INTERLEAVED layout: gt box with original index g = p*(G/4)+k lives at
    // slot 4k+p. Lane with part p at iteration k reads slot 4k+p -> the 4
    // distinct addresses per warp are 16 B apart (boxes) / 4 B apart (areas):
    // disjoint banks -> conflict-free LDS (R5's 4-way same-bank conflict,
    // 1024 B apart, is what collapsed issue to 27%).
    __shared__ float4 s_gti[G_MAX];    // interleaved boxes
    __shared__ float  s_areai[G_MAX];  // interleaved areas
    __shared__ float4 s_gt[G_MAX];     // original order (output gather)
    __shared__ float  s_lab[G_MAX];    // original order

    const int t = threadIdx.x;
    const int Gq = G / SPLIT;
    if (t < G) {
        float4 b = gt[t];
        s_gt[t] = b;
        float area = __fmul_rn(__fsub_rn(b.z, b.x), __fsub_rn(b.w, b.y));
        const int pos = SPLIT * (t % Gq) + (t / Gq);   // interleave map
        s_gti[pos]   = b;
        s_areai[pos] = area;
        // labels >= 1, so little-endian i64 => word 1 (hi word of elem 0) == 0
        int is64 = (gtl32[1] == 0) ? 1 : 0;
        s_lab[t] = (float)gtl32[is64 ? (2 * t) : t];
    }
    __syncthreads();

    const int part = t & (SPLIT - 1);
    const int n    = blockIdx.x * (BLOCK / SPLIT) + (t >> 2);
    const int ni   = (n < N) ? n : (N - 1);      // clamp tail loads; store guarded

    const float4 p = props[ni];
    const float parea = __fmul_rn(__fsub_rn(p.z, p.x), __fsub_rn(p.w, p.y));

    // Sentinel (bestI=0, bestS=1): only strictly-positive inter can win; an
    // all-zero row resolves to idx 0 after the merge, iou = 0/(1-0) = 0 ->
    // label -1, box gt[0], matching jnp.argmax-of-zeros.
    float bestI = 0.0f, bestS = 1.0f;
    const int gs = part * Gq;
    int bestIdx = gs;

    #pragma unroll 8
    for (int k = 0; k < Gq; ++k) {
        const int ii = SPLIT * k + part;          // conflict-free slot
        const float4 gb = s_gti[ii];
        const float  ag = s_areai[ii];
        float x1 = fmaxf(gb.x, p.x);
        float y1 = fmaxf(gb.y, p.y);
        float x2 = fminf(gb.z, p.z);
        float y2 = fminf(gb.w, p.w);
        float dx = fmaxf(__fsub_rn(x2, x1), 0.0f);
        float dy = __fsub_rn(y2, y1);             // UNclamped (see proof)
        // inter' = max(dx,0)*dy. If dy<0: inter' <= 0 -> d <= 0 -> never taken
        // (bestI>=0, S>0; at sentinel fl(neg*1) < 0). If taken, inter' > 0
        // forces dy > 0, so inter' equals the reference's clamped inter bitwise.
        float inter = __fmul_rn(dx, dy);
        float S     = __fadd_rn(ag, parea);       // area_g + parea
        // iou = inter/(S - inter) monotone in inter/S (S > 0):
        //   i1/(S1-i1) > i2/(S2-i2)  <=>  i1*S2 > i2*S1  (cross terms cancel)
        // FFMA sign of the cross-difference (~1 ulp of exact); strict > keeps
        // the earlier index (jnp.argmax first-max semantics).
        float d = __fmaf_rn(inter, bestS, -__fmul_rn(bestI, S));
        bool take = d > 0.0f;
        bestI   = take ? inter  : bestI;
        bestS   = take ? S      : bestS;
        bestIdx = take ? gs + k : bestIdx;
    }

    // Tree merge across the 4 lanes sharing this proposal. Tie-safe rule:
    // take partner iff strictly greater, or exactly tied with a lower index —
    // every lane then holds the first-max of the merged range (proven R5).
    #pragma unroll
    for (int m = 1; m < SPLIT; m <<= 1) {
        float oI   = __shfl_xor_sync(0xffffffffu, bestI,   m);
        float oS   = __shfl_xor_sync(0xffffffffu, bestS,   m);
        int   oIdx = __shfl_xor_sync(0xffffffffu, bestIdx, m);
        float dm = __fmaf_rn(oI, bestS, -__fmul_rn(bestI, oS));
        bool take = (dm > 0.0f) || (dm == 0.0f && oIdx < bestIdx);
        bestI   = take ? oI   : bestI;
        bestS   = take ? oS   : bestS;
        bestIdx = take ? oIdx : bestIdx;
    }

    if (part == 0 && n < N) {
        // uni = fl(bestS - bestI) == reference's fl(fl(a1+a2) - inter);
        // single IEEE division -> bitwise-equal iou for the winning pair.
        float uni = __fsub_rn(bestS, bestI);
        float iou = __fdiv_rn(bestI, uni);
        float lab = s_lab[bestIdx];
        if (iou < 0.5f) lab = (iou >= 0.1f) ? 0.0f : -1.0f;
        if (out_labels) out_labels[n] = lab;
        if (out_boxes)  out_boxes[n]  = s_gt[bestIdx];
    }
}

// Generic fallback (R4 logic) for shapes the fast path doesn't cover.
__global__ __launch_bounds__(256)
void roi_dense_kernel(const float4* __restrict__ props,
                      const float4* __restrict__ gt,
                      const int*    __restrict__ gtl32,
                      float*        __restrict__ out_labels,
                      float4*       __restrict__ out_boxes,
                      int N, int G)
{
    __shared__ float4 s_gt[G_MAX];
    __shared__ float  s_area[G_MAX];
    __shared__ float  s_lab[G_MAX];
    const int t = threadIdx.x;
    if (t < G && t < G_MAX) {
        float4 b = gt[t];
        s_gt[t]   = b;
        s_area[t] = __fmul_rn(__fsub_rn(b.z, b.x), __fsub_rn(b.w, b.y));
        int is64 = (G >= 2 && gtl32[1] == 0) ? 1 : 0;
        s_lab[t] = (float)gtl32[is64 ? (2 * t) : t];
    }
    __syncthreads();
    const int n  = blockIdx.x * 256 + t;
    const int ni = (n < N) ? n : (N - 1);
    const float4 p = props[ni];
    const float parea = __fmul_rn(__fsub_rn(p.z, p.x), __fsub_rn(p.w, p.y));
    float bestI = 0.0f, bestS = 1.0f;
    int bestIdx = 0;
    for (int g = 0; g < G; ++g) {
        const float4 gb = s_gt[g];
        float x1 = fmaxf(gb.x, p.x), y1 = fmaxf(gb.y, p.y);
        float x2 = fminf(gb.z, p.z), y2 = fminf(gb.w, p.w);
        float dx = fmaxf(__fsub_rn(x2, x1), 0.0f);
        float dy = fmaxf(__fsub_rn(y2, y1), 0.0f);
        float inter = __fmul_rn(dx, dy);
        float S     = __fadd_rn(s_area[g], parea);
        float d = __fmaf_rn(inter, bestS, -__fmul_rn(bestI, S));
        bool take = d > 0.0f;
        bestI = take ? inter : bestI;
        bestS = take ? S : bestS;
        bestIdx = take ? g : bestIdx;
    }
    if (n < N) {
        float uni = __fsub_rn(bestS, bestI);
        float iou = __fdiv_rn(bestI, uni);
        float lab = s_lab[bestIdx];
        if (iou < 0.5f) lab = (iou >= 0.1f) ? 0.0f : -1.0f;
        if (out_labels) out_labels[n] = lab;
        if (out_boxes)  out_boxes[n]  = s_gt[bestIdx];
    }
}

extern "C" void kernel_launch(void* const* d_in, const int* in_sizes, int n_in,
                              void* d_out, int out_size)
{
    const float4* props = (const float4*)d_in[0];
    const float4* gt    = (const float4*)d_in[1];
    const int*    gtl   = (const int*)d_in[2];

    const int N = in_sizes[0] / 4;
    const int G = in_sizes[1] / 4;

    float*  out       = (float*)d_out;
    float*  out_label = nullptr;
    float4* out_boxes = nullptr;
    if (out_size == 5 * N) {            // [labels (N) ; boxes (4N)] as f32
        out_label = out;
        out_boxes = (float4*)(out + N); // 16B-aligned since N % 4 == 0
    } else if (out_size == 4 * N) {     // boxes only
        out_boxes = (float4*)out;
    } else {                            // labels only
        out_label = out;
    }

    if (G <= G_MAX && G >= 8 && (G % 8) == 0) {
        const int props_per_block = BLOCK / SPLIT;
        const int grid = (N + props_per_block - 1) / props_per_block;
        roi_match_kernel<<<grid, BLOCK>>>(props, gt, gtl, out_label, out_boxes, N, G);
    } else {
        roi_dense_kernel<<<(N + 255) / 256, 256>>>(props, gt, gtl,
                                                   out_label, out_boxes, N, G);
    }
}

// round 13
// speedup vs baseline: 1.0867x; 1.0867x over previous
#include <cuda_runtime.h>
#include <cuda_bf16.h>

#define G_MAX 128
#define BLOCK 128

// Lane pairs (2k, 2k+1) share one proposal: even lane scans g in [0, G/2),
// odd lane scans [G/2, G); merged with one shfl + exact compare.
// BLOCK=128 -> 3126 blocks (~21/SM) minimizes the last-wave tail that held
// the 256-thread variant at occ 72%.
__global__ __launch_bounds__(BLOCK)
void roi_match_kernel(const float4* __restrict__ props,
                      const float4* __restrict__ gt,
                      const int*    __restrict__ gtl32,   // gt labels, i32 or i64 (auto-detect)
                      float*        __restrict__ out_labels,
                      float4*       __restrict__ out_boxes,
                      int N, int G)
{
    __shared__ float4 s_gt[G_MAX];
    __shared__ float4 s_areav[G_MAX / 4];   // areas batched 4-wide
    __shared__ float  s_lab[G_MAX];

    const int t = threadIdx.x;
    if (t < G) {
        float4 b = gt[t];
        s_gt[t] = b;
        ((float*)s_areav)[t] = __fmul_rn(__fsub_rn(b.z, b.x), __fsub_rn(b.w, b.y));
        // labels >= 1, so little-endian i64 => word 1 (hi word of elem 0) == 0
        int is64 = (gtl32[1] == 0) ? 1 : 0;
        s_lab[t] = (float)gtl32[is64 ? (2 * t) : t];
    }
    __syncthreads();

    const int half = t & 1;
    const int n    = blockIdx.x * (BLOCK / 2) + (t >> 1);
    const int ni   = (n < N) ? n : (N - 1);          // clamp tail loads; store guarded

    const float4 p = props[ni];
    const float parea = __fmul_rn(__fsub_rn(p.z, p.x), __fsub_rn(p.w, p.y));

    // Sentinel (bestI=0, bestS=1): only strictly-positive inter can win; an
    // all-zero row resolves to idx 0, iou = 0/(1-0) = 0 -> label -1, box gt[0],
    // matching jnp.argmax-of-zeros.
    float bestI = 0.0f, bestS = 1.0f;
    const int gs = half * (G >> 1);
    int bestIdx = gs;

    // G/2 assumed multiple of 4 (G % 8 == 0; checked on host). 4 chunks of 4
    // gts per branch: ~2 KB body, fits L0 I$; loop overhead amortized 1/16.
    #pragma unroll 4
    for (int q = 0; q < (G >> 3); ++q) {
        const int g0 = gs + q * 4;
        const float4 av = s_areav[g0 >> 2];          // one LDS.128 per 4 areas
        const float areas[4] = { av.x, av.y, av.z, av.w };
        #pragma unroll
        for (int k = 0; k < 4; ++k) {
            const int g = g0 + k;
            const float4 gb = s_gt[g];               // broadcast LDS.128
            float x1 = fmaxf(gb.x, p.x);
            float y1 = fmaxf(gb.y, p.y);
            float x2 = fminf(gb.z, p.z);
            float y2 = fminf(gb.w, p.w);
            float dx = fmaxf(__fsub_rn(x2, x1), 0.0f);
            float dy = __fsub_rn(y2, y1);            // UNclamped (see proof)
            // inter' = max(dx,0)*dy. If dy<0: inter' <= 0 -> d <= 0 -> never
            // taken (bestI>=0, S>0; at sentinel fl(neg*1) < 0). If taken,
            // inter' > 0 forces dy > 0, so inter' equals the reference's
            // clamped inter bitwise. Saves one FMNMX on the alu pipe.
            float inter = __fmul_rn(dx, dy);
            float S     = __fadd_rn(areas[k], parea);    // area_g + parea
            // iou = inter/(S - inter) monotone in inter/S (S > 0):
            //   i1/(S1-i1) > i2/(S2-i2)  <=>  i1*S2 > i2*S1  (cross terms cancel)
            // FFMA sign of the cross-difference (~1 ulp of exact); strict >
            // keeps the earlier index (jnp.argmax first-max semantics).
            float d = __fmaf_rn(inter, bestS, -__fmul_rn(bestI, S));
            bool take = d > 0.0f;
            bestI   = take ? inter : bestI;
            bestS   = take ? S     : bestS;
            bestIdx = take ? g     : bestIdx;
        }
    }

    // Pair merge: take partner iff strictly greater; the even lane holds the
    // lower g range, so ties keep the smaller index. Even lane stores.
    float oI   = __shfl_xor_sync(0xffffffffu, bestI, 1);
    float oS   = __shfl_xor_sync(0xffffffffu, bestS, 1);
    int   oIdx = __shfl_xor_sync(0xffffffffu, bestIdx, 1);
    float dm = __fmaf_rn(oI, bestS, -__fmul_rn(bestI, oS));
    if (dm > 0.0f) { bestI = oI; bestS = oS; bestIdx = oIdx; }

    if (half == 0 && n < N) {
        // uni = fl(bestS - bestI) == reference's fl(fl(a1+a2) - inter);
        // single IEEE division -> bitwise-equal iou for the winning pair.
        float uni = __fsub_rn(bestS, bestI);
        float iou = __fdiv_rn(bestI, uni);
        float lab = s_lab[bestIdx];
        if (iou < 0.5f) lab = (iou >= 0.1f) ? 0.0f : -1.0f;
        if (out_labels) out_labels[n] = lab;
        if (out_boxes)  out_boxes[n]  = s_gt[bestIdx];
    }
}

// Generic fallback (R4 logic) for shapes the fast path doesn't cover.
__global__ __launch_bounds__(256)
void roi_dense_kernel(const float4* __restrict__ props,
                      const float4* __restrict__ gt,
                      const int*    __restrict__ gtl32,
                      float*        __restrict__ out_labels,
                      float4*       __restrict__ out_boxes,
                      int N, int G)
{
    __shared__ float4 s_gt[G_MAX];
    __shared__ float  s_area[G_MAX];
    __shared__ float  s_lab[G_MAX];
    const int t = threadIdx.x;
    if (t < G && t < G_MAX) {
        float4 b = gt[t];
        s_gt[t]   = b;
        s_area[t] = __fmul_rn(__fsub_rn(b.z, b.x), __fsub_rn(b.w, b.y));
        int is64 = (G >= 2 && gtl32[1] == 0) ? 1 : 0;
        s_lab[t] = (float)gtl32[is64 ? (2 * t) : t];
    }
    __syncthreads();
    const int n  = blockIdx.x * 256 + t;
    const int ni = (n < N) ? n : (N - 1);
    const float4 p = props[ni];
    const float parea = __fmul_rn(__fsub_rn(p.z, p.x), __fsub_rn(p.w, p.y));
    float bestI = 0.0f, bestS = 1.0f;
    int bestIdx = 0;
    for (int g = 0; g < G; ++g) {
        const float4 gb = s_gt[g];
        float x1 = fmaxf(gb.x, p.x), y1 = fmaxf(gb.y, p.y);
        float x2 = fminf(gb.z, p.z), y2 = fminf(gb.w, p.w);
        float dx = fmaxf(__fsub_rn(x2, x1), 0.0f);
        float dy = fmaxf(__fsub_rn(y2, y1), 0.0f);
        float inter = __fmul_rn(dx, dy);
        float S     = __fadd_rn(s_area[g], parea);
        float d = __fmaf_rn(inter, bestS, -__fmul_rn(bestI, S));
        bool take = d > 0.0f;
        bestI = take ? inter : bestI;
        bestS = take ? S : bestS;
        bestIdx = take ? g : bestIdx;
    }
    if (n < N) {
        float uni = __fsub_rn(bestS, bestI);
        float iou = __fdiv_rn(bestI, uni);
        float lab = s_lab[bestIdx];
        if (iou < 0.5f) lab = (iou >= 0.1f) ? 0.0f : -1.0f;
        if (out_labels) out_labels[n] = lab;
        if (out_boxes)  out_boxes[n]  = s_gt[bestIdx];
    }
}

extern "C" void kernel_launch(void* const* d_in, const int* in_sizes, int n_in,
                              void* d_out, int out_size)
{
    const float4* props = (const float4*)d_in[0];
    const float4* gt    = (const float4*)d_in[1];
    const int*    gtl   = (const int*)d_in[2];

    const int N = in_sizes[0] / 4;
    const int G = in_sizes[1] / 4;

    float*  out       = (float*)d_out;
    float*  out_label = nullptr;
    float4* out_boxes = nullptr;
    if (out_size == 5 * N) {            // [labels (N) ; boxes (4N)] as f32
        out_label = out;
        out_boxes = (float4*)(out + N); // 16B-aligned since N % 4 == 0
    } else if (out_size == 4 * N) {     // boxes only
        out_boxes = (float4*)out;
    } else {                            // labels only
        out_label = out;
    }

    if (G <= G_MAX && G >= 8 && (G % 8) == 0) {
        const int props_per_block = BLOCK / 2;
        const int grid = (N + props_per_block - 1) / props_per_block;
        roi_match_kernel<<<grid, BLOCK>>>(props, gt, gtl, out_label, out_boxes, N, G);
    } else {
        roi_dense_kernel<<<(N + 255) / 256, 256>>>(props, gt, gtl,
                                                   out_label, out_boxes, N, G);
    }
}

// round 14
// speedup vs baseline: 1.1916x; 1.0965x over previous
#include <cuda_runtime.h>
#include <cuda_bf16.h>

#define G_MAX 128
#define BLOCK 128

// Lane pairs (2k, 2k+1) share one proposal: even lane scans g in [0, G/2),
// odd lane scans [G/2, G); merged with one shfl + exact compare.
// gt boxes are stored INTERLEAVED (orig g = half*G/2 + k -> slot 2k+half) so
// the two distinct LDS.128 addresses per warp are 16 B apart -> disjoint
// banks -> conflict-free (the half-split layout put them 1024 B apart = same
// banks = 2-way conflict on every load; L1 pipe measured 65%).
__global__ __launch_bounds__(BLOCK)
void roi_match_kernel(const float4* __restrict__ props,
                      const float4* __restrict__ gt,
                      const int*    __restrict__ gtl32,   // gt labels, i32 or i64 (auto-detect)
                      float*        __restrict__ out_labels,
                      float4*       __restrict__ out_boxes,
                      int N, int G)
{
    __shared__ float4 s_gti[G_MAX];      // interleaved boxes: slot 2k+half
    __shared__ float  s_area2[2][68];    // per-half areas; 16 B pad de-conflicts
    __shared__ float4 s_gt[G_MAX];       // original order (output gather)
    __shared__ float  s_lab[G_MAX];

    const int t = threadIdx.x;
    const int Gh = G >> 1;
    if (t < G) {
        float4 b = gt[t];
        s_gt[t] = b;
        const int h = t / Gh, k = t % Gh;
        s_gti[(k << 1) | h] = b;
        s_area2[h][k] = __fmul_rn(__fsub_rn(b.z, b.x), __fsub_rn(b.w, b.y));
        // labels >= 1, so little-endian i64 => word 1 (hi word of elem 0) == 0
        int is64 = (gtl32[1] == 0) ? 1 : 0;
        s_lab[t] = (float)gtl32[is64 ? (2 * t) : t];
    }
    __syncthreads();

    const int half = t & 1;
    const int n    = blockIdx.x * (BLOCK / 2) + (t >> 1);
    const int ni   = (n < N) ? n : (N - 1);          // clamp tail loads; store guarded

    const float4 p = props[ni];
    const float parea = __fmul_rn(__fsub_rn(p.z, p.x), __fsub_rn(p.w, p.y));

    // Sentinel (bestI=0, bestS=1): only strictly-positive inter can win; an
    // all-zero row resolves to idx 0, iou = 0/(1-0) = 0 -> label -1, box gt[0],
    // matching jnp.argmax-of-zeros.
    float bestI = 0.0f, bestS = 1.0f;
    const int gs = half * Gh;
    int bestIdx = gs;

    // Gh assumed multiple of 4 (G % 8 == 0; checked on host).
    #pragma unroll 4
    for (int q = 0; q < (G >> 3); ++q) {
        // one conflict-free LDS.128 per 4 areas (even/odd bases 272 B apart)
        const float4 av = *(const float4*)&s_area2[half][q << 2];
        const float areas[4] = { av.x, av.y, av.z, av.w };
        #pragma unroll
        for (int j = 0; j < 4; ++j) {
            const int k = (q << 2) + j;
            const float4 gb = s_gti[(k << 1) | half];   // conflict-free slot
            float x1 = fmaxf(gb.x, p.x);
            float y1 = fmaxf(gb.y, p.y);
            float x2 = fminf(gb.z, p.z);
            float y2 = fminf(gb.w, p.w);
            float dx = fmaxf(__fsub_rn(x2, x1), 0.0f);
            float dy = __fsub_rn(y2, y1);               // UNclamped (see proof)
            // inter' = max(dx,0)*dy. If dy<0: inter' <= 0 -> d <= 0 -> never
            // taken (bestI>=0, S>0; at sentinel fl(neg*1) < 0). If taken,
            // inter' > 0 forces dy > 0, so inter' equals the reference's
            // clamped inter bitwise.
            float inter = __fmul_rn(dx, dy);
            float S     = __fadd_rn(areas[j], parea);   // area_g + parea
            // iou = inter/(S - inter) monotone in inter/S (S > 0):
            //   i1/(S1-i1) > i2/(S2-i2)  <=>  i1*S2 > i2*S1  (cross terms cancel)
            // FFMA sign of the cross-difference (~1 ulp of exact); strict >
            // keeps the earlier index (jnp.argmax first-max semantics).
            float d = __fmaf_rn(inter, bestS, -__fmul_rn(bestI, S));
            bool take = d > 0.0f;
            bestI   = take ? inter  : bestI;
            bestS   = take ? S      : bestS;
            bestIdx = take ? gs + k : bestIdx;
        }
    }

    // Pair merge: take partner iff strictly greater; the even lane holds the
    // lower g range, so ties keep the smaller index. Even lane stores.
    float oI   = __shfl_xor_sync(0xffffffffu, bestI, 1);
    float oS   = __shfl_xor_sync(0xffffffffu, bestS, 1);
    int   oIdx = __shfl_xor_sync(0xffffffffu, bestIdx, 1);
    float dm = __fmaf_rn(oI, bestS, -__fmul_rn(bestI, oS));
    if (dm > 0.0f) { bestI = oI; bestS = oS; bestIdx = oIdx; }

    if (half == 0 && n < N) {
        // uni = fl(bestS - bestI) == reference's fl(fl(a1+a2) - inter);
        // single IEEE division -> bitwise-equal iou for the winning pair.
        float uni = __fsub_rn(bestS, bestI);
        float iou = __fdiv_rn(bestI, uni);
        float lab = s_lab[bestIdx];
        if (iou < 0.5f) lab = (iou >= 0.1f) ? 0.0f : -1.0f;
        if (out_labels) out_labels[n] = lab;
        if (out_boxes)  out_boxes[n]  = s_gt[bestIdx];
    }
}

// Generic fallback (R4 logic) for shapes the fast path doesn't cover.
__global__ __launch_bounds__(256)
void roi_dense_kernel(const float4* __restrict__ props,
                      const float4* __restrict__ gt,
                      const int*    __restrict__ gtl32,
                      float*        __restrict__ out_labels,
                      float4*       __restrict__ out_boxes,
                      int N, int G)
{
    __shared__ float4 s_gt[G_MAX];
    __shared__ float  s_area[G_MAX];
    __shared__ float  s_lab[G_MAX];
    const int t = threadIdx.x;
    if (t < G && t < G_MAX) {
        float4 b = gt[t];
        s_gt[t]   = b;
        s_area[t] = __fmul_rn(__fsub_rn(b.z, b.x), __fsub_rn(b.w, b.y));
        int is64 = (G >= 2 && gtl32[1] == 0) ? 1 : 0;
        s_lab[t] = (float)gtl32[is64 ? (2 * t) : t];
    }
    __syncthreads();
    const int n  = blockIdx.x * 256 + t;
    const int ni = (n < N) ? n : (N - 1);
    const float4 p = props[ni];
    const float parea = __fmul_rn(__fsub_rn(p.z, p.x), __fsub_rn(p.w, p.y));
    float bestI = 0.0f, bestS = 1.0f;
    int bestIdx = 0;
    for (int g = 0; g < G; ++g) {
        const float4 gb = s_gt[g];
        float x1 = fmaxf(gb.x, p.x), y1 = fmaxf(gb.y, p.y);
        float x2 = fminf(gb.z, p.z), y2 = fminf(gb.w, p.w);
        float dx = fmaxf(__fsub_rn(x2, x1), 0.0f);
        float dy = fmaxf(__fsub_rn(y2, y1), 0.0f);
        float inter = __fmul_rn(dx, dy);
        float S     = __fadd_rn(s_area[g], parea);
        float d = __fmaf_rn(inter, bestS, -__fmul_rn(bestI, S));
        bool take = d > 0.0f;
        bestI = take ? inter : bestI;
        bestS = take ? S : bestS;
        bestIdx = take ? g : bestIdx;
    }
    if (n < N) {
        float uni = __fsub_rn(bestS, bestI);
        float iou = __fdiv_rn(bestI, uni);
        float lab = s_lab[bestIdx];
        if (iou < 0.5f) lab = (iou >= 0.1f) ? 0.0f : -1.0f;
        if (out_labels) out_labels[n] = lab;
        if (out_boxes)  out_boxes[n]  = s_gt[bestIdx];
    }
}

extern "C" void kernel_launch(void* const* d_in, const int* in_sizes, int n_in,
                              void* d_out, int out_size)
{
    const float4* props = (const float4*)d_in[0];
    const float4* gt    = (const float4*)d_in[1];
    const int*    gtl   = (const int*)d_in[2];

    const int N = in_sizes[0] / 4;
    const int G = in_sizes[1] / 4;

    float*  out       = (float*)d_out;
    float*  out_label = nullptr;
    float4* out_boxes = nullptr;
    if (out_size == 5 * N) {            // [labels (N) ; boxes (4N)] as f32
        out_label = out;
        out_boxes = (float4*)(out + N); // 16B-aligned since N % 4 == 0
    } else if (out_size == 4 * N) {     // boxes only
        out_boxes = (float4*)out;
    } else {                            // labels only
        out_label = out;
    }

    if (G <= G_MAX && G >= 8 && (G % 8) == 0) {
        const int props_per_block = BLOCK / 2;
        const int grid = (N + props_per_block - 1) / props_per_block;
        roi_match_kernel<<<grid, BLOCK>>>(props, gt, gtl, out_label, out_boxes, N, G);
    } else {
        roi_dense_kernel<<<(N + 255) / 256, 256>>>(props, gt, gtl,
                                                   out_label, out_boxes, N, G);
    }
}